// round 3
// baseline (speedup 1.0000x reference)
#include <cuda_runtime.h>
#include <cstdint>
#include <cstddef>

// Problem constants
constexpr int Himg = 192;
constexpr int Wimg = 320;
constexpr int HWimg = Himg * Wimg;
constexpr int BATCH = 2;
constexpr int NFEAT = 64;
constexpr int OMCH  = 216;   // 3 * DG * KK

// Scratch (device globals — no allocation allowed)
__device__ float g_off1[(size_t)BATCH * NFEAT * HWimg];
__device__ float g_off2[(size_t)BATCH * NFEAT * HWimg];
__device__ float g_om  [(size_t)BATCH * OMCH  * HWimg];

// ---------------------------------------------------------------------------
// packed f32x2 helpers (Blackwell dual-issue fp32 path)
// ---------------------------------------------------------------------------
__device__ __forceinline__ unsigned long long pack2(float lo, float hi) {
    unsigned long long r;
    asm("mov.b64 %0, {%1, %2};" : "=l"(r) : "f"(lo), "f"(hi));
    return r;
}
__device__ __forceinline__ void fma2(unsigned long long& d,
                                     unsigned long long a, unsigned long long b) {
    asm("fma.rn.f32x2 %0, %1, %2, %0;" : "+l"(d) : "l"(a), "l"(b));
}
__device__ __forceinline__ float2 unpack2(unsigned long long v) {
    float lo, hi;
    asm("mov.b64 {%0, %1}, %2;" : "=f"(lo), "=f"(hi) : "l"(v));
    return make_float2(lo, hi);
}
__device__ __forceinline__ float lrelu(float x) { return x >= 0.f ? x : 0.1f * x; }

// ---------------------------------------------------------------------------
// 3x3 same-padding conv, NCHW.  MODE 0: single input tensor of CIN channels.
// MODE 1: implicit concat(warped[64], ref[64], flows[2]) = 130 channels.
// Tile: 64 wide x 32 tall output pixels, 8 output channels per block.
// Per thread: 2 cols x 4 rows x 8 cout accumulated as f32x2 (over the 2 cols).
// ---------------------------------------------------------------------------
template<int CIN, int COUT, int MODE, bool DO_LRELU>
__global__ __launch_bounds__(256, 2)
void conv3x3_kernel(const float* __restrict__ in0, const float* __restrict__ in1,
                    const float* __restrict__ in2, const float* __restrict__ wgt,
                    const float* __restrict__ bias, float* __restrict__ out)
{
    constexpr int CI_BLK = 4;
    __shared__ __align__(16) float s_in[CI_BLK][34][68];
    __shared__ unsigned long long s_w[CI_BLK][9][8];   // (w,w) pairs

    const int t  = threadIdx.x;
    const int tx = t & 31;
    const int ty = t >> 5;
    const int tbx = blockIdx.x % 5;        // Wimg/64 = 5 tiles
    const int tby = blockIdx.x / 5;        // Himg/32 = 6 tiles
    const int x0 = tbx * 64;
    const int y0 = tby * 32;
    const int b  = blockIdx.y;
    const int co0 = blockIdx.z * 8;

    unsigned long long acc[8][4];
#pragma unroll
    for (int co = 0; co < 8; ++co)
#pragma unroll
        for (int r = 0; r < 4; ++r) acc[co][r] = 0ull;

    for (int ci0 = 0; ci0 < CIN; ci0 += CI_BLK) {
        if (ci0) __syncthreads();

        // ---- load input halo tile (34 x 66 per channel), zero padded ----
        for (int idx = t; idx < CI_BLK * 34 * 66; idx += 256) {
            int c   = idx / (34 * 66);
            int rem = idx - c * (34 * 66);
            int r   = rem / 66;
            int cc  = rem - r * 66;
            int ci  = ci0 + c;
            int gy  = y0 - 1 + r;
            int gx  = x0 - 1 + cc;
            float v = 0.f;
            if (ci < CIN && (unsigned)gy < (unsigned)Himg && (unsigned)gx < (unsigned)Wimg) {
                const float* p;
                if (MODE == 0) {
                    p = in0 + (size_t)(b * CIN + ci) * HWimg;
                } else {
                    if (ci < 64)        p = in0 + (size_t)(b * 64 + ci) * HWimg;
                    else if (ci < 128)  p = in1 + (size_t)(b * 64 + (ci - 64)) * HWimg;
                    else                p = in2 + (size_t)(b * 2 + (ci - 128)) * HWimg;
                }
                v = p[gy * Wimg + gx];
            }
            s_in[c][r][cc] = v;
        }

        // ---- load weights (duplicated pairs), zero padded on channel tail ----
        for (int idx = t; idx < CI_BLK * 72; idx += 256) {
            int c   = idx / 72;
            int rem = idx - c * 72;
            int co  = rem / 9;
            int k   = rem - co * 9;
            float wv = 0.f;
            if (ci0 + c < CIN)
                wv = wgt[(size_t)(co0 + co) * (CIN * 9) + (ci0 + c) * 9 + k];
            s_w[c][k][co] = pack2(wv, wv);
        }
        __syncthreads();

        // ---- compute ----
#pragma unroll
        for (int c = 0; c < CI_BLK; ++c) {
#pragma unroll
            for (int dy = 0; dy < 3; ++dy) {
                unsigned long long p0[4], p1[4], p2[4];
#pragma unroll
                for (int r = 0; r < 4; ++r) {
                    const float* q = &s_in[c][ty + 8 * r + dy][2 * tx];
                    float2 a  = *reinterpret_cast<const float2*>(q);
                    float2 bb = *reinterpret_cast<const float2*>(q + 2);
                    p0[r] = pack2(a.x, a.y);
                    p1[r] = pack2(a.y, bb.x);
                    p2[r] = pack2(bb.x, bb.y);
                }
#pragma unroll
                for (int dx = 0; dx < 3; ++dx) {
#pragma unroll
                    for (int co = 0; co < 8; ++co) {
                        unsigned long long wv = s_w[c][dy * 3 + dx][co];
#pragma unroll
                        for (int r = 0; r < 4; ++r) {
                            unsigned long long pv = (dx == 0) ? p0[r] : (dx == 1) ? p1[r] : p2[r];
                            fma2(acc[co][r], pv, wv);
                        }
                    }
                }
            }
        }
    }

    // ---- epilogue: bias (+lrelu), vectorized store ----
#pragma unroll
    for (int co = 0; co < 8; ++co) {
        float bb = bias[co0 + co];
        float* op = out + (size_t)(b * COUT + co0 + co) * HWimg;
#pragma unroll
        for (int r = 0; r < 4; ++r) {
            float2 v = unpack2(acc[co][r]);
            v.x += bb; v.y += bb;
            if (DO_LRELU) { v.x = lrelu(v.x); v.y = lrelu(v.y); }
            *reinterpret_cast<float2*>(op + (y0 + ty + 8 * r) * Wimg + x0 + 2 * tx) = v;
        }
    }
}

// ---------------------------------------------------------------------------
// Flow-guided deformable conv.
// Block: 256 threads = 16x16 output pixels, one pixel per thread, all 64 cout.
// Loops over 8 deform groups; per group stages a 49x49 halo tile (halo=16)
// of the 8 group channels in SMEM and the 8x9x64 weight slice (o-contiguous).
// Bilinear gathers come from SMEM (LDS); rare out-of-halo corners fall back
// to bounds-checked global loads. Inner GEMV is f32x2-packed over cout pairs.
// ---------------------------------------------------------------------------
__global__ __launch_bounds__(256, 2)
void dcn_kernel(const float* __restrict__ xin, const float* __restrict__ flows,
                const float* __restrict__ om, const float* __restrict__ wdcn,
                const float* __restrict__ bias, float* __restrict__ out)
{
    extern __shared__ float smem[];
    float* s_x  = smem;            // 8 * 49 * 50 = 19600 floats
    float* s_wt = smem + 19600;    // 9 * 8 * 64  =  4608 floats

    const int t   = threadIdx.x;
    const int tbx = blockIdx.x % 20;   // Wimg/16
    const int tby = blockIdx.x / 20;   // Himg/16
    const int x0  = tbx * 16;
    const int y0  = tby * 16;
    const int b   = blockIdx.y;
    const int px  = x0 + (t & 15);
    const int pyq = y0 + (t >> 4);
    const int ry0 = y0 - 16;
    const int rx0 = x0 - 16;

    const float fl_x = flows[(size_t)(b * 2 + 0) * HWimg + pyq * Wimg + px];
    const float fl_y = flows[(size_t)(b * 2 + 1) * HWimg + pyq * Wimg + px];
    const float* omp = om + (size_t)b * OMCH * HWimg + pyq * Wimg + px;
    const float* xb  = xin + (size_t)b * 64 * HWimg;

    unsigned long long acc[32];
#pragma unroll
    for (int i = 0; i < 32; ++i) acc[i] = 0ull;

    for (int g = 0; g < 8; ++g) {
        if (g) __syncthreads();

        // stage x region for this group's 8 channels (zero outside image)
        for (int idx = t; idx < 8 * 49 * 49; idx += 256) {
            int c   = idx / 2401;
            int rem = idx - c * 2401;
            int r   = rem / 49;
            int cc  = rem - r * 49;
            int gy  = ry0 + r;
            int gx  = rx0 + cc;
            float v = 0.f;
            if ((unsigned)gy < (unsigned)Himg && (unsigned)gx < (unsigned)Wimg)
                v = xb[(size_t)(g * 8 + c) * HWimg + gy * Wimg + gx];
            s_x[(c * 49 + r) * 50 + cc] = v;
        }
        // stage weight slice, transposed to [k][c][o] (o contiguous)
        for (int idx = t; idx < 4608; idx += 256) {
            int o   = idx / 72;
            int rem = idx - o * 72;
            int c   = rem / 9;
            int k   = rem - c * 9;
            s_wt[(k * 8 + c) * 64 + o] = wdcn[(size_t)o * 576 + (g * 8 + c) * 9 + k];
        }
        __syncthreads();

#pragma unroll 3
        for (int k = 0; k < 9; ++k) {
            float offy = omp[(size_t)(g * 18 + 2 * k) * HWimg] + fl_y;
            float offx = omp[(size_t)(g * 18 + 2 * k + 1) * HWimg] + fl_x;
            float mraw = omp[(size_t)(144 + g * 9 + k) * HWimg];
            float m = 1.f / (1.f + __expf(-mraw));

            float pyf = (float)(pyq + (k / 3) - 1) + offy;
            float pxf = (float)(px  + (k % 3) - 1) + offx;
            float fy = floorf(pyf), fx = floorf(pxf);
            int iy = (int)fy, ix = (int)fx;
            float wy = pyf - fy, wx = pxf - fx;

            // mask folded into bilinear coefficients
            float c11 = wy * wx * m;
            float c10 = wy * m - c11;
            float c01 = wx * m - c11;
            float c00 = m - wy * m - c01;

            bool ok = (iy >= ry0) && (iy <= ry0 + 47) && (ix >= rx0) && (ix <= rx0 + 47);
            int base = (iy - ry0) * 50 + (ix - rx0);

#pragma unroll
            for (int c = 0; c < 8; ++c) {
                float v00, v01, v10, v11;
                if (ok) {
                    const float* xc = s_x + c * 2450 + base;
                    v00 = xc[0];  v01 = xc[1];
                    v10 = xc[50]; v11 = xc[51];
                } else {
                    const float* xp = xb + (size_t)(g * 8 + c) * HWimg;
                    v00 = ((unsigned)iy < (unsigned)Himg && (unsigned)ix < (unsigned)Wimg)
                              ? xp[iy * Wimg + ix] : 0.f;
                    v01 = ((unsigned)iy < (unsigned)Himg && (unsigned)(ix + 1) < (unsigned)Wimg)
                              ? xp[iy * Wimg + ix + 1] : 0.f;
                    v10 = ((unsigned)(iy + 1) < (unsigned)Himg && (unsigned)ix < (unsigned)Wimg)
                              ? xp[(iy + 1) * Wimg + ix] : 0.f;
                    v11 = ((unsigned)(iy + 1) < (unsigned)Himg && (unsigned)(ix + 1) < (unsigned)Wimg)
                              ? xp[(iy + 1) * Wimg + ix + 1] : 0.f;
                }
                float val = fmaf(v00, c00, fmaf(v01, c01, fmaf(v10, c10, v11 * c11)));
                unsigned long long vp = pack2(val, val);
                const unsigned long long* wrow =
                    reinterpret_cast<const unsigned long long*>(s_wt + (k * 8 + c) * 64);
#pragma unroll
                for (int o2 = 0; o2 < 32; ++o2)
                    fma2(acc[o2], vp, wrow[o2]);
            }
        }
    }

    // epilogue: bias + lrelu + store
#pragma unroll
    for (int o2 = 0; o2 < 32; ++o2) {
        float2 v = unpack2(acc[o2]);
        int o = 2 * o2;
        float r0 = lrelu(v.x + bias[o]);
        float r1 = lrelu(v.y + bias[o + 1]);
        out[(size_t)(b * 64 + o)     * HWimg + pyq * Wimg + px] = r0;
        out[(size_t)(b * 64 + o + 1) * HWimg + pyq * Wimg + px] = r1;
    }
}

// ---------------------------------------------------------------------------
// Launch
// ---------------------------------------------------------------------------
extern "C" void kernel_launch(void* const* d_in, const int* in_sizes, int n_in,
                              void* d_out, int out_size)
{
    (void)in_sizes; (void)n_in; (void)out_size;
    const float* nbr    = (const float*)d_in[0];
    const float* warped = (const float*)d_in[1];
    const float* ref    = (const float*)d_in[2];
    const float* flows  = (const float*)d_in[3];
    const float* w1     = (const float*)d_in[4];
    const float* b1     = (const float*)d_in[5];
    const float* w2     = (const float*)d_in[6];
    const float* b2     = (const float*)d_in[7];
    const float* w_om   = (const float*)d_in[8];
    const float* b_om   = (const float*)d_in[9];
    const float* w_dcn  = (const float*)d_in[10];
    const float* b_dcn  = (const float*)d_in[11];
    float* out = (float*)d_out;

    float *p1, *p2, *pm;
    cudaGetSymbolAddress((void**)&p1, g_off1);
    cudaGetSymbolAddress((void**)&p2, g_off2);
    cudaGetSymbolAddress((void**)&pm, g_om);

    // conv1: concat(warped, ref, flows) [130ch] -> 64, lrelu
    conv3x3_kernel<130, 64, 1, true><<<dim3(30, BATCH, 8), 256>>>(
        warped, ref, flows, w1, b1, p1);
    // conv2: 64 -> 64, lrelu
    conv3x3_kernel<64, 64, 0, true><<<dim3(30, BATCH, 8), 256>>>(
        p1, nullptr, nullptr, w2, b2, p2);
    // offset/mask conv: 64 -> 216, no activation
    conv3x3_kernel<64, 216, 0, false><<<dim3(30, BATCH, 27), 256>>>(
        p2, nullptr, nullptr, w_om, b_om, pm);

    // deformable conv + lrelu
    constexpr int DCN_SMEM = (19600 + 4608) * 4;  // 96832 bytes
    cudaFuncSetAttribute(dcn_kernel, cudaFuncAttributeMaxDynamicSharedMemorySize, DCN_SMEM);
    dcn_kernel<<<dim3(240, BATCH), 256, DCN_SMEM>>>(nbr, flows, pm, w_dcn, b_dcn, out);
}

// round 4
// speedup vs baseline: 1.0059x; 1.0059x over previous
#include <cuda_runtime.h>
#include <cstdint>
#include <cstddef>

// Problem constants
constexpr int Himg = 192;
constexpr int Wimg = 320;
constexpr int HWimg = Himg * Wimg;
constexpr int BATCH = 2;
constexpr int NFEAT = 64;
constexpr int OMCH  = 216;   // 3 * DG * KK

// Scratch (device globals — no allocation allowed)
__device__ float g_off1[(size_t)BATCH * NFEAT * HWimg];
__device__ float g_off2[(size_t)BATCH * NFEAT * HWimg];
__device__ float g_om  [(size_t)BATCH * OMCH  * HWimg];

// ---------------------------------------------------------------------------
// packed f32x2 helpers (Blackwell dual-issue fp32 path)
// ---------------------------------------------------------------------------
__device__ __forceinline__ unsigned long long pack2(float lo, float hi) {
    unsigned long long r;
    asm("mov.b64 %0, {%1, %2};" : "=l"(r) : "f"(lo), "f"(hi));
    return r;
}
__device__ __forceinline__ void fma2(unsigned long long& d,
                                     unsigned long long a, unsigned long long b) {
    asm("fma.rn.f32x2 %0, %1, %2, %0;" : "+l"(d) : "l"(a), "l"(b));
}
__device__ __forceinline__ float2 unpack2(unsigned long long v) {
    float lo, hi;
    asm("mov.b64 {%0, %1}, %2;" : "=f"(lo), "=f"(hi) : "l"(v));
    return make_float2(lo, hi);
}
__device__ __forceinline__ float lrelu(float x) { return x >= 0.f ? x : 0.1f * x; }

// ---------------------------------------------------------------------------
// 3x3 same-padding conv, NCHW.  MODE 0: single input tensor of CIN channels.
// MODE 1: implicit concat(warped[64], ref[64], flows[2]) = 130 channels.
// Tile: 64 wide x 32 tall output pixels, 8 output channels per block.
// Per thread: 2 cols x 4 rows x 8 cout accumulated as f32x2 (over the 2 cols).
// ---------------------------------------------------------------------------
template<int CIN, int COUT, int MODE, bool DO_LRELU>
__global__ __launch_bounds__(256, 2)
void conv3x3_kernel(const float* __restrict__ in0, const float* __restrict__ in1,
                    const float* __restrict__ in2, const float* __restrict__ wgt,
                    const float* __restrict__ bias, float* __restrict__ out)
{
    constexpr int CI_BLK = 4;
    __shared__ __align__(16) float s_in[CI_BLK][34][68];
    __shared__ unsigned long long s_w[CI_BLK][9][8];   // (w,w) pairs

    const int t  = threadIdx.x;
    const int tx = t & 31;
    const int ty = t >> 5;
    const int tbx = blockIdx.x % 5;        // Wimg/64 = 5 tiles
    const int tby = blockIdx.x / 5;        // Himg/32 = 6 tiles
    const int x0 = tbx * 64;
    const int y0 = tby * 32;
    const int b  = blockIdx.y;
    const int co0 = blockIdx.z * 8;

    unsigned long long acc[8][4];
#pragma unroll
    for (int co = 0; co < 8; ++co)
#pragma unroll
        for (int r = 0; r < 4; ++r) acc[co][r] = 0ull;

    for (int ci0 = 0; ci0 < CIN; ci0 += CI_BLK) {
        if (ci0) __syncthreads();

        // ---- load input halo tile (34 x 66 per channel), zero padded ----
        for (int idx = t; idx < CI_BLK * 34 * 66; idx += 256) {
            int c   = idx / (34 * 66);
            int rem = idx - c * (34 * 66);
            int r   = rem / 66;
            int cc  = rem - r * 66;
            int ci  = ci0 + c;
            int gy  = y0 - 1 + r;
            int gx  = x0 - 1 + cc;
            float v = 0.f;
            if (ci < CIN && (unsigned)gy < (unsigned)Himg && (unsigned)gx < (unsigned)Wimg) {
                const float* p;
                if (MODE == 0) {
                    p = in0 + (size_t)(b * CIN + ci) * HWimg;
                } else {
                    if (ci < 64)        p = in0 + (size_t)(b * 64 + ci) * HWimg;
                    else if (ci < 128)  p = in1 + (size_t)(b * 64 + (ci - 64)) * HWimg;
                    else                p = in2 + (size_t)(b * 2 + (ci - 128)) * HWimg;
                }
                v = p[gy * Wimg + gx];
            }
            s_in[c][r][cc] = v;
        }

        // ---- load weights (duplicated pairs), zero padded on channel tail ----
        for (int idx = t; idx < CI_BLK * 72; idx += 256) {
            int c   = idx / 72;
            int rem = idx - c * 72;
            int co  = rem / 9;
            int k   = rem - co * 9;
            float wv = 0.f;
            if (ci0 + c < CIN)
                wv = wgt[(size_t)(co0 + co) * (CIN * 9) + (ci0 + c) * 9 + k];
            s_w[c][k][co] = pack2(wv, wv);
        }
        __syncthreads();

        // ---- compute ----
#pragma unroll
        for (int c = 0; c < CI_BLK; ++c) {
#pragma unroll
            for (int dy = 0; dy < 3; ++dy) {
                unsigned long long p0[4], p1[4], p2[4];
#pragma unroll
                for (int r = 0; r < 4; ++r) {
                    const float* q = &s_in[c][ty + 8 * r + dy][2 * tx];
                    float2 a  = *reinterpret_cast<const float2*>(q);
                    float2 bb = *reinterpret_cast<const float2*>(q + 2);
                    p0[r] = pack2(a.x, a.y);
                    p1[r] = pack2(a.y, bb.x);
                    p2[r] = pack2(bb.x, bb.y);
                }
#pragma unroll
                for (int dx = 0; dx < 3; ++dx) {
#pragma unroll
                    for (int co = 0; co < 8; ++co) {
                        unsigned long long wv = s_w[c][dy * 3 + dx][co];
#pragma unroll
                        for (int r = 0; r < 4; ++r) {
                            unsigned long long pv = (dx == 0) ? p0[r] : (dx == 1) ? p1[r] : p2[r];
                            fma2(acc[co][r], pv, wv);
                        }
                    }
                }
            }
        }
    }

    // ---- epilogue: bias (+lrelu), vectorized store ----
#pragma unroll
    for (int co = 0; co < 8; ++co) {
        float bb = bias[co0 + co];
        float* op = out + (size_t)(b * COUT + co0 + co) * HWimg;
#pragma unroll
        for (int r = 0; r < 4; ++r) {
            float2 v = unpack2(acc[co][r]);
            v.x += bb; v.y += bb;
            if (DO_LRELU) { v.x = lrelu(v.x); v.y = lrelu(v.y); }
            *reinterpret_cast<float2*>(op + (y0 + ty + 8 * r) * Wimg + x0 + 2 * tx) = v;
        }
    }
}

// ---------------------------------------------------------------------------
// Flow-guided deformable conv.
// Block: 256 threads = 16x16 output pixels, one pixel per thread, all 64 cout.
// Loops over 8 deform groups; per group stages a 49x49 halo tile (halo=16)
// of the 8 group channels in SMEM and the 8x9x64 weight slice (o-contiguous).
// Bilinear gathers come from SMEM (LDS); rare out-of-halo corners fall back
// to bounds-checked global loads. Inner GEMV is f32x2-packed over cout pairs.
// ---------------------------------------------------------------------------
__global__ __launch_bounds__(256, 2)
void dcn_kernel(const float* __restrict__ xin, const float* __restrict__ flows,
                const float* __restrict__ om, const float* __restrict__ wdcn,
                const float* __restrict__ bias, float* __restrict__ out)
{
    extern __shared__ float smem[];
    float* s_x  = smem;            // 8 * 49 * 50 = 19600 floats
    float* s_wt = smem + 19600;    // 9 * 8 * 64  =  4608 floats

    const int t   = threadIdx.x;
    const int tbx = blockIdx.x % 20;   // Wimg/16
    const int tby = blockIdx.x / 20;   // Himg/16
    const int x0  = tbx * 16;
    const int y0  = tby * 16;
    const int b   = blockIdx.y;
    const int px  = x0 + (t & 15);
    const int pyq = y0 + (t >> 4);
    const int ry0 = y0 - 16;
    const int rx0 = x0 - 16;

    const float fl_x = flows[(size_t)(b * 2 + 0) * HWimg + pyq * Wimg + px];
    const float fl_y = flows[(size_t)(b * 2 + 1) * HWimg + pyq * Wimg + px];
    const float* omp = om + (size_t)b * OMCH * HWimg + pyq * Wimg + px;
    const float* xb  = xin + (size_t)b * 64 * HWimg;

    unsigned long long acc[32];
#pragma unroll
    for (int i = 0; i < 32; ++i) acc[i] = 0ull;

    for (int g = 0; g < 8; ++g) {
        if (g) __syncthreads();

        // stage x region for this group's 8 channels (zero outside image)
        for (int idx = t; idx < 8 * 49 * 49; idx += 256) {
            int c   = idx / 2401;
            int rem = idx - c * 2401;
            int r   = rem / 49;
            int cc  = rem - r * 49;
            int gy  = ry0 + r;
            int gx  = rx0 + cc;
            float v = 0.f;
            if ((unsigned)gy < (unsigned)Himg && (unsigned)gx < (unsigned)Wimg)
                v = xb[(size_t)(g * 8 + c) * HWimg + gy * Wimg + gx];
            s_x[(c * 49 + r) * 50 + cc] = v;
        }
        // stage weight slice, transposed to [k][c][o] (o contiguous)
        for (int idx = t; idx < 4608; idx += 256) {
            int o   = idx / 72;
            int rem = idx - o * 72;
            int c   = rem / 9;
            int k   = rem - c * 9;
            s_wt[(k * 8 + c) * 64 + o] = wdcn[(size_t)o * 576 + (g * 8 + c) * 9 + k];
        }
        __syncthreads();

#pragma unroll 3
        for (int k = 0; k < 9; ++k) {
            float offy = omp[(size_t)(g * 18 + 2 * k) * HWimg] + fl_y;
            float offx = omp[(size_t)(g * 18 + 2 * k + 1) * HWimg] + fl_x;
            float mraw = omp[(size_t)(144 + g * 9 + k) * HWimg];
            float m = 1.f / (1.f + __expf(-mraw));

            float pyf = (float)(pyq + (k / 3) - 1) + offy;
            float pxf = (float)(px  + (k % 3) - 1) + offx;
            float fy = floorf(pyf), fx = floorf(pxf);
            int iy = (int)fy, ix = (int)fx;
            float wy = pyf - fy, wx = pxf - fx;

            // mask folded into bilinear coefficients
            float c11 = wy * wx * m;
            float c10 = wy * m - c11;
            float c01 = wx * m - c11;
            float c00 = m - wy * m - c01;

            bool ok = (iy >= ry0) && (iy <= ry0 + 47) && (ix >= rx0) && (ix <= rx0 + 47);
            int base = (iy - ry0) * 50 + (ix - rx0);

#pragma unroll
            for (int c = 0; c < 8; ++c) {
                float v00, v01, v10, v11;
                if (ok) {
                    const float* xc = s_x + c * 2450 + base;
                    v00 = xc[0];  v01 = xc[1];
                    v10 = xc[50]; v11 = xc[51];
                } else {
                    const float* xp = xb + (size_t)(g * 8 + c) * HWimg;
                    v00 = ((unsigned)iy < (unsigned)Himg && (unsigned)ix < (unsigned)Wimg)
                              ? xp[iy * Wimg + ix] : 0.f;
                    v01 = ((unsigned)iy < (unsigned)Himg && (unsigned)(ix + 1) < (unsigned)Wimg)
                              ? xp[iy * Wimg + ix + 1] : 0.f;
                    v10 = ((unsigned)(iy + 1) < (unsigned)Himg && (unsigned)ix < (unsigned)Wimg)
                              ? xp[(iy + 1) * Wimg + ix] : 0.f;
                    v11 = ((unsigned)(iy + 1) < (unsigned)Himg && (unsigned)(ix + 1) < (unsigned)Wimg)
                              ? xp[(iy + 1) * Wimg + ix + 1] : 0.f;
                }
                float val = fmaf(v00, c00, fmaf(v01, c01, fmaf(v10, c10, v11 * c11)));
                unsigned long long vp = pack2(val, val);
                const unsigned long long* wrow =
                    reinterpret_cast<const unsigned long long*>(s_wt + (k * 8 + c) * 64);
#pragma unroll
                for (int o2 = 0; o2 < 32; ++o2)
                    fma2(acc[o2], vp, wrow[o2]);
            }
        }
    }

    // epilogue: bias + lrelu + store
#pragma unroll
    for (int o2 = 0; o2 < 32; ++o2) {
        float2 v = unpack2(acc[o2]);
        int o = 2 * o2;
        float r0 = lrelu(v.x + bias[o]);
        float r1 = lrelu(v.y + bias[o + 1]);
        out[(size_t)(b * 64 + o)     * HWimg + pyq * Wimg + px] = r0;
        out[(size_t)(b * 64 + o + 1) * HWimg + pyq * Wimg + px] = r1;
    }
}

// ---------------------------------------------------------------------------
// Launch
// ---------------------------------------------------------------------------
extern "C" void kernel_launch(void* const* d_in, const int* in_sizes, int n_in,
                              void* d_out, int out_size)
{
    (void)in_sizes; (void)n_in; (void)out_size;
    const float* nbr    = (const float*)d_in[0];
    const float* warped = (const float*)d_in[1];
    const float* ref    = (const float*)d_in[2];
    const float* flows  = (const float*)d_in[3];
    const float* w1     = (const float*)d_in[4];
    const float* b1     = (const float*)d_in[5];
    const float* w2     = (const float*)d_in[6];
    const float* b2     = (const float*)d_in[7];
    const float* w_om   = (const float*)d_in[8];
    const float* b_om   = (const float*)d_in[9];
    const float* w_dcn  = (const float*)d_in[10];
    const float* b_dcn  = (const float*)d_in[11];
    float* out = (float*)d_out;

    float *p1, *p2, *pm;
    cudaGetSymbolAddress((void**)&p1, g_off1);
    cudaGetSymbolAddress((void**)&p2, g_off2);
    cudaGetSymbolAddress((void**)&pm, g_om);

    // conv1: concat(warped, ref, flows) [130ch] -> 64, lrelu
    conv3x3_kernel<130, 64, 1, true><<<dim3(30, BATCH, 8), 256>>>(
        warped, ref, flows, w1, b1, p1);
    // conv2: 64 -> 64, lrelu
    conv3x3_kernel<64, 64, 0, true><<<dim3(30, BATCH, 8), 256>>>(
        p1, nullptr, nullptr, w2, b2, p2);
    // offset/mask conv: 64 -> 216, no activation
    conv3x3_kernel<64, 216, 0, false><<<dim3(30, BATCH, 27), 256>>>(
        p2, nullptr, nullptr, w_om, b_om, pm);

    // deformable conv + lrelu
    constexpr int DCN_SMEM = (19600 + 4608) * 4;  // 96832 bytes
    cudaFuncSetAttribute(dcn_kernel, cudaFuncAttributeMaxDynamicSharedMemorySize, DCN_SMEM);
    dcn_kernel<<<dim3(240, BATCH), 256, DCN_SMEM>>>(nbr, flows, pm, w_dcn, b_dcn, out);
}

// round 11
// speedup vs baseline: 2.3761x; 2.3621x over previous
#include <cuda_runtime.h>
#include <cuda_bf16.h>
#include <cstdint>
#include <cstddef>

constexpr int H = 192;
constexpr int W = 320;
constexpr int HW = H * W;
constexpr int B_ = 2;
constexpr int OMCH = 216;

// ---- device scratch ----
__device__ __align__(16) __nv_bfloat16 g_in1h[(size_t)B_ * HW * 144];
__device__ __align__(16) __nv_bfloat16 g_in1l[(size_t)B_ * HW * 144];
__device__ __align__(16) __nv_bfloat16 g_x2h[(size_t)B_ * HW * 64];
__device__ __align__(16) __nv_bfloat16 g_x2l[(size_t)B_ * HW * 64];
__device__ __align__(16) __nv_bfloat16 g_x3h[(size_t)B_ * HW * 64];
__device__ __align__(16) __nv_bfloat16 g_x3l[(size_t)B_ * HW * 64];
__device__ float g_om[(size_t)B_ * OMCH * HW];

// prepacked weights: rows of 24 bf16 (16 data + 8 pad), [tap][cb][n]
// set1: 9*9*64 rows; set2: 9*4*64; set3: 9*4*224
constexpr int W1ROWS = 9 * 9 * 64;
constexpr int W2ROWS = 9 * 4 * 64;
constexpr int W3ROWS = 9 * 4 * 224;
constexpr int WROWS = W1ROWS + W2ROWS + W3ROWS;
constexpr size_t W1OFF = 0;
constexpr size_t W2OFF = (size_t)W1ROWS * 24;
constexpr size_t W3OFF = (size_t)(W1ROWS + W2ROWS) * 24;
__device__ __align__(16) __nv_bfloat16 g_wbh[(size_t)WROWS * 24];
__device__ __align__(16) __nv_bfloat16 g_wbl[(size_t)WROWS * 24];

// ---- helpers ----
__device__ __forceinline__ uint32_t smem_u32(const void* p) {
    uint32_t a;
    asm("{ .reg .u64 t; cvta.to.shared.u64 t, %1; cvt.u32.u64 %0, t; }" : "=r"(a) : "l"(p));
    return a;
}
__device__ __forceinline__ void ldsm4(uint32_t r[4], uint32_t a) {
    asm volatile("ldmatrix.sync.aligned.m8n8.x4.shared.b16 {%0,%1,%2,%3}, [%4];"
        : "=r"(r[0]), "=r"(r[1]), "=r"(r[2]), "=r"(r[3]) : "r"(a));
}
__device__ __forceinline__ void ldsm2(uint32_t r[2], uint32_t a) {
    asm volatile("ldmatrix.sync.aligned.m8n8.x2.shared.b16 {%0,%1}, [%2];"
        : "=r"(r[0]), "=r"(r[1]) : "r"(a));
}
__device__ __forceinline__ void mma16816(float c[4], const uint32_t a[4], uint32_t b0, uint32_t b1) {
    asm volatile("mma.sync.aligned.m16n8k16.row.col.f32.bf16.bf16.f32 "
        "{%0,%1,%2,%3},{%4,%5,%6,%7},{%8,%9},{%0,%1,%2,%3};"
        : "+f"(c[0]), "+f"(c[1]), "+f"(c[2]), "+f"(c[3])
        : "r"(a[0]), "r"(a[1]), "r"(a[2]), "r"(a[3]), "r"(b0), "r"(b1));
}
__device__ __forceinline__ float lrelu(float x) { return x >= 0.f ? x : 0.1f * x; }
__device__ __forceinline__ unsigned long long pack2(float lo, float hi) {
    unsigned long long r; asm("mov.b64 %0, {%1, %2};" : "=l"(r) : "f"(lo), "f"(hi)); return r;
}
__device__ __forceinline__ void fma2(unsigned long long& d, unsigned long long a, unsigned long long b) {
    asm("fma.rn.f32x2 %0, %1, %2, %0;" : "+l"(d) : "l"(a), "l"(b));
}
__device__ __forceinline__ float2 unpack2(unsigned long long v) {
    float lo, hi; asm("mov.b64 {%0, %1}, %2;" : "=f"(lo), "=f"(hi) : "l"(v)); return make_float2(lo, hi);
}
__device__ __forceinline__ void split_bf16(float v, __nv_bfloat16& h, __nv_bfloat16& l) {
    h = __float2bfloat16(v);
    l = __float2bfloat16(v - __bfloat162float(h));
}

// ---- input converter: NCHW f32 concat -> [b][p][144] bf16 hi/lo ----
__global__ __launch_bounds__(256) void convert_in1(
    const float* __restrict__ wp, const float* __restrict__ rf, const float* __restrict__ fl)
{
    __shared__ float s[64 * 145];
    const int nb = HW / 64;
    const int b = blockIdx.x / nb;
    const int p0 = (blockIdx.x % nb) * 64;
    for (int idx = threadIdx.x; idx < 64 * 144; idx += 256) {
        int px = idx & 63, ci = idx >> 6;
        float v = 0.f;
        if (ci < 64)       v = wp[(size_t)(b * 64 + ci) * HW + p0 + px];
        else if (ci < 128) v = rf[(size_t)(b * 64 + ci - 64) * HW + p0 + px];
        else if (ci < 130) v = fl[(size_t)(b * 2 + ci - 128) * HW + p0 + px];
        s[px * 145 + ci] = v;
    }
    __syncthreads();
    size_t base = ((size_t)b * HW + p0) * 144;
    for (int o = threadIdx.x; o < 64 * 144; o += 256) {
        int px = o / 144, ci = o - px * 144;
        __nv_bfloat16 hb, lb;
        split_bf16(s[px * 145 + ci], hb, lb);
        g_in1h[base + o] = hb;
        g_in1l[base + o] = lb;
    }
}

// ---- weight prepack ----
__global__ __launch_bounds__(256) void prepackW(
    const float* __restrict__ w1, const float* __restrict__ w2, const float* __restrict__ wom)
{
    for (int row = blockIdx.x * 256 + threadIdx.x; row < WROWS; row += gridDim.x * 256) {
        int tap, cb, n, CIN, COUT;
        const float* w;
        if (row < W1ROWS) {
            int r = row; tap = r / (9 * 64); cb = (r / 64) % 9; n = r & 63;
            CIN = 130; COUT = 64; w = w1;
        } else if (row < W1ROWS + W2ROWS) {
            int r = row - W1ROWS; tap = r / (4 * 64); cb = (r / 64) % 4; n = r & 63;
            CIN = 64; COUT = 64; w = w2;
        } else {
            int r = row - W1ROWS - W2ROWS; tap = r / (4 * 224); cb = (r / 224) % 4; n = r % 224;
            CIN = 64; COUT = 216; w = wom;
        }
        size_t o = (size_t)row * 24;
        for (int j = 0; j < 16; ++j) {
            int ci = cb * 16 + j;
            float v = 0.f;
            if (ci < CIN && n < COUT) v = w[((size_t)n * CIN + ci) * 9 + tap];
            __nv_bfloat16 hb, lb;
            split_bf16(v, hb, lb);
            g_wbh[o + j] = hb;
            g_wbl[o + j] = lb;
        }
        for (int j = 16; j < 24; ++j) { g_wbh[o + j] = __float2bfloat16(0.f); g_wbl[o + j] = __float2bfloat16(0.f); }
    }
}

// ---- tensor-core conv via mma.sync (bf16 hi/lo, fp32 accum) ----
template<int CINB, int COUT, int NPAD, bool OUT_BF16, bool DO_LRELU>
__global__ __launch_bounds__(256)
void convMMA(const __nv_bfloat16* __restrict__ inh, const __nv_bfloat16* __restrict__ inl,
             const __nv_bfloat16* __restrict__ wbh, const __nv_bfloat16* __restrict__ wbl,
             const float* __restrict__ bias,
             __nv_bfloat16* __restrict__ outh, __nv_bfloat16* __restrict__ outl,
             float* __restrict__ outf)
{
    constexpr int WN = (NPAD == 64) ? 2 : 4;
    constexpr int MROWS = 8 / WN;               // 4 or 2 pixel rows per block
    constexpr int NFR = NPAD / (8 * WN);        // 4 or 7
    constexpr int CINP = CINB * 16;
    constexpr int AROWS = MROWS + 2;
    constexpr int ASZ = AROWS * 34 * 48;
    constexpr int BSZ = NPAD * 48;

    extern __shared__ __align__(16) unsigned char sm[];
    unsigned char* sAh = sm;
    unsigned char* sAl = sm + ASZ;
    unsigned char* sBh = sm + 2 * ASZ;
    unsigned char* sBl = sm + 2 * ASZ + BSZ;
    const uint32_t aAh = smem_u32(sAh), aAl = smem_u32(sAl);
    const uint32_t aBh = smem_u32(sBh), aBl = smem_u32(sBl);

    const int tid = threadIdx.x;
    const int lane = tid & 31, warp = tid >> 5;
    const int wm = warp / WN, wn = warp % WN;
    const int x0 = (blockIdx.x % 10) * 32;
    const int y0 = (blockIdx.x / 10) * MROWS;
    const int b = blockIdx.y;

    float acc[2][NFR][4];
#pragma unroll
    for (int i = 0; i < 2; ++i)
#pragma unroll
        for (int f = 0; f < NFR; ++f)
#pragma unroll
            for (int r = 0; r < 4; ++r) acc[i][f][r] = 0.f;

    const size_t inbase = (size_t)b * HW * CINP;

    for (int cb = 0; cb < CINB; ++cb) {
        for (int tap = 0; tap < 9; ++tap) {
            __syncthreads();
            if (tap == 0) {
                for (int it = tid; it < AROWS * 34 * 2; it += 256) {
                    int half = it & 1, pix = it >> 1;
                    int tr = pix / 34, tx = pix - tr * 34;
                    int gy = y0 - 1 + tr, gx = x0 - 1 + tx;
                    uint4 vh = {0, 0, 0, 0}, vl = {0, 0, 0, 0};
                    if ((unsigned)gy < (unsigned)H && (unsigned)gx < (unsigned)W) {
                        size_t o = inbase + (size_t)(gy * W + gx) * CINP + cb * 16 + half * 8;
                        vh = *reinterpret_cast<const uint4*>(inh + o);
                        vl = *reinterpret_cast<const uint4*>(inl + o);
                    }
                    int so = pix * 48 + half * 16;
                    *reinterpret_cast<uint4*>(sAh + so) = vh;
                    *reinterpret_cast<uint4*>(sAl + so) = vl;
                }
            }
            {
                size_t wo = (size_t)(tap * CINB + cb) * NPAD * 24;
                const uint4* gh = reinterpret_cast<const uint4*>(wbh + wo);
                const uint4* gl = reinterpret_cast<const uint4*>(wbl + wo);
                for (int it = tid; it < NPAD * 3; it += 256) {
                    reinterpret_cast<uint4*>(sBh)[it] = gh[it];
                    reinterpret_cast<uint4*>(sBl)[it] = gl[it];
                }
            }
            __syncthreads();

            const int dy = tap / 3, dx = tap % 3;
            uint32_t ah[2][4], al[2][4];
#pragma unroll
            for (int i = 0; i < 2; ++i) {
                int row = (wm + dy) * 34 + i * 16 + dx + (lane & 15);
                uint32_t ad = row * 48 + ((lane >> 4) << 4);
                ldsm4(ah[i], aAh + ad);
                ldsm4(al[i], aAl + ad);
            }
#pragma unroll
            for (int jj = 0; jj < NFR / 2; ++jj) {
                int n0 = wn * (NFR * 8) + jj * 16;
                uint32_t bd = (uint32_t)(n0 + (lane & 7) + ((lane >> 4) << 3)) * 48 + (((lane >> 3) & 1) << 4);
                uint32_t bh[4], bl[4];
                ldsm4(bh, aBh + bd);
                ldsm4(bl, aBl + bd);
#pragma unroll
                for (int h = 0; h < 2; ++h) {
                    int f = jj * 2 + h;
#pragma unroll
                    for (int i = 0; i < 2; ++i) {
                        mma16816(acc[i][f], ah[i], bh[2 * h], bh[2 * h + 1]);
                        mma16816(acc[i][f], al[i], bh[2 * h], bh[2 * h + 1]);
                        mma16816(acc[i][f], ah[i], bl[2 * h], bl[2 * h + 1]);
                    }
                }
            }
            if (NFR & 1) {
                constexpr int f = NFR - 1;
                int n0 = wn * (NFR * 8) + f * 8;
                uint32_t bd = (uint32_t)(n0 + (lane & 7)) * 48 + (((lane >> 3) & 1) << 4);
                uint32_t bh[2], bl[2];
                ldsm2(bh, aBh + bd);
                ldsm2(bl, aBl + bd);
#pragma unroll
                for (int i = 0; i < 2; ++i) {
                    mma16816(acc[i][f], ah[i], bh[0], bh[1]);
                    mma16816(acc[i][f], al[i], bh[0], bh[1]);
                    mma16816(acc[i][f], ah[i], bl[0], bl[1]);
                }
            }
        }
    }

    // epilogue
#pragma unroll
    for (int i = 0; i < 2; ++i) {
#pragma unroll
        for (int f = 0; f < NFR; ++f) {
            int n = wn * (NFR * 8) + f * 8 + (lane & 3) * 2;
            float b0 = 0.f, b1 = 0.f;
            if (n < COUT) { b0 = bias[n]; b1 = bias[n + 1]; }
#pragma unroll
            for (int h = 0; h < 2; ++h) {
                int rx = i * 16 + (lane >> 2) + h * 8;
                int y = y0 + wm, x = x0 + rx;
                size_t p = (size_t)y * W + x;
                float v0 = acc[i][f][2 * h] + b0;
                float v1 = acc[i][f][2 * h + 1] + b1;
                if (DO_LRELU) { v0 = lrelu(v0); v1 = lrelu(v1); }
                if (OUT_BF16) {
                    size_t o = ((size_t)b * HW + p) * 64 + n;
                    __nv_bfloat16 h0, l0, h1, l1;
                    split_bf16(v0, h0, l0);
                    split_bf16(v1, h1, l1);
                    *reinterpret_cast<__nv_bfloat162*>(outh + o) = __halves2bfloat162(h0, h1);
                    *reinterpret_cast<__nv_bfloat162*>(outl + o) = __halves2bfloat162(l0, l1);
                } else if (n < COUT) {
                    outf[((size_t)b * COUT + n) * HW + p] = v0;
                    outf[((size_t)b * COUT + n + 1) * HW + p] = v1;
                }
            }
        }
    }
}

// ---- flow-guided deformable conv (f32x2 scalar path) ----
__global__ __launch_bounds__(256, 2)
void dcn_kernel(const float* __restrict__ xin, const float* __restrict__ flows,
                const float* __restrict__ om, const float* __restrict__ wdcn,
                const float* __restrict__ bias, float* __restrict__ out)
{
    extern __shared__ float smem[];
    float* s_x  = smem;
    float* s_wt = smem + 19600;

    const int t = threadIdx.x;
    const int x0 = (blockIdx.x % 20) * 16, y0 = (blockIdx.x / 20) * 16;
    const int b = blockIdx.y;
    const int px = x0 + (t & 15), pyq = y0 + (t >> 4);
    const int ry0 = y0 - 16, rx0 = x0 - 16;

    const float fl_x = flows[(size_t)(b * 2 + 0) * HW + pyq * W + px];
    const float fl_y = flows[(size_t)(b * 2 + 1) * HW + pyq * W + px];
    const float* omp = om + (size_t)b * OMCH * HW + pyq * W + px;
    const float* xb  = xin + (size_t)b * 64 * HW;

    unsigned long long acc[32];
#pragma unroll
    for (int i = 0; i < 32; ++i) acc[i] = 0ull;

    for (int g = 0; g < 8; ++g) {
        if (g) __syncthreads();
        for (int idx = t; idx < 8 * 49 * 49; idx += 256) {
            int c = idx / 2401, rem = idx - c * 2401;
            int r = rem / 49, cc = rem - r * 49;
            int gy = ry0 + r, gx = rx0 + cc;
            float v = 0.f;
            if ((unsigned)gy < (unsigned)H && (unsigned)gx < (unsigned)W)
                v = xb[(size_t)(g * 8 + c) * HW + gy * W + gx];
            s_x[(c * 49 + r) * 50 + cc] = v;
        }
        for (int idx = t; idx < 4608; idx += 256) {
            int o = idx / 72, rem = idx - o * 72;
            int c = rem / 9, k = rem - c * 9;
            s_wt[(k * 8 + c) * 64 + o] = wdcn[(size_t)o * 576 + (g * 8 + c) * 9 + k];
        }
        __syncthreads();

#pragma unroll 3
        for (int k = 0; k < 9; ++k) {
            float offy = omp[(size_t)(g * 18 + 2 * k) * HW] + fl_y;
            float offx = omp[(size_t)(g * 18 + 2 * k + 1) * HW] + fl_x;
            float mraw = omp[(size_t)(144 + g * 9 + k) * HW];
            float m = 1.f / (1.f + __expf(-mraw));

            float pyf = (float)(pyq + (k / 3) - 1) + offy;
            float pxf = (float)(px + (k % 3) - 1) + offx;
            float fy = floorf(pyf), fx = floorf(pxf);
            int iy = (int)fy, ix = (int)fx;
            float wy = pyf - fy, wx = pxf - fx;

            float c11 = wy * wx * m;
            float c10 = wy * m - c11;
            float c01 = wx * m - c11;
            float c00 = m - wy * m - c01;

            bool ok = (iy >= ry0) && (iy <= ry0 + 47) && (ix >= rx0) && (ix <= rx0 + 47);
            int base = (iy - ry0) * 50 + (ix - rx0);

#pragma unroll
            for (int c = 0; c < 8; ++c) {
                float v00, v01, v10, v11;
                if (ok) {
                    const float* xc = s_x + c * 2450 + base;
                    v00 = xc[0];  v01 = xc[1];
                    v10 = xc[50]; v11 = xc[51];
                } else {
                    const float* xp = xb + (size_t)(g * 8 + c) * HW;
                    v00 = ((unsigned)iy < (unsigned)H && (unsigned)ix < (unsigned)W) ? xp[iy * W + ix] : 0.f;
                    v01 = ((unsigned)iy < (unsigned)H && (unsigned)(ix + 1) < (unsigned)W) ? xp[iy * W + ix + 1] : 0.f;
                    v10 = ((unsigned)(iy + 1) < (unsigned)H && (unsigned)ix < (unsigned)W) ? xp[(iy + 1) * W + ix] : 0.f;
                    v11 = ((unsigned)(iy + 1) < (unsigned)H && (unsigned)(ix + 1) < (unsigned)W) ? xp[(iy + 1) * W + ix + 1] : 0.f;
                }
                float val = fmaf(v00, c00, fmaf(v01, c01, fmaf(v10, c10, v11 * c11)));
                unsigned long long vp = pack2(val, val);
                const ulonglong2* wrow = reinterpret_cast<const ulonglong2*>(s_wt + (k * 8 + c) * 64);
#pragma unroll
                for (int o4 = 0; o4 < 16; ++o4) {
                    ulonglong2 wv = wrow[o4];
                    fma2(acc[2 * o4],     vp, wv.x);
                    fma2(acc[2 * o4 + 1], vp, wv.y);
                }
            }
        }
    }

#pragma unroll
    for (int o2 = 0; o2 < 32; ++o2) {
        float2 v = unpack2(acc[o2]);
        int o = 2 * o2;
        out[(size_t)(b * 64 + o)     * HW + pyq * W + px] = lrelu(v.x + bias[o]);
        out[(size_t)(b * 64 + o + 1) * HW + pyq * W + px] = lrelu(v.y + bias[o + 1]);
    }
}

// ---- launch ----
extern "C" void kernel_launch(void* const* d_in, const int* in_sizes, int n_in,
                              void* d_out, int out_size)
{
    (void)in_sizes; (void)n_in; (void)out_size;
    const float* nbr    = (const float*)d_in[0];
    const float* warped = (const float*)d_in[1];
    const float* ref    = (const float*)d_in[2];
    const float* flows  = (const float*)d_in[3];
    const float* w1     = (const float*)d_in[4];
    const float* b1     = (const float*)d_in[5];
    const float* w2     = (const float*)d_in[6];
    const float* b2     = (const float*)d_in[7];
    const float* w_om   = (const float*)d_in[8];
    const float* b_om   = (const float*)d_in[9];
    const float* w_dcn  = (const float*)d_in[10];
    const float* b_dcn  = (const float*)d_in[11];
    float* out = (float*)d_out;

    __nv_bfloat16 *in1h, *in1l, *x2h, *x2l, *x3h, *x3l, *wbh, *wbl;
    float* pm;
    cudaGetSymbolAddress((void**)&in1h, g_in1h);
    cudaGetSymbolAddress((void**)&in1l, g_in1l);
    cudaGetSymbolAddress((void**)&x2h, g_x2h);
    cudaGetSymbolAddress((void**)&x2l, g_x2l);
    cudaGetSymbolAddress((void**)&x3h, g_x3h);
    cudaGetSymbolAddress((void**)&x3l, g_x3l);
    cudaGetSymbolAddress((void**)&wbh, g_wbh);
    cudaGetSymbolAddress((void**)&wbl, g_wbl);
    cudaGetSymbolAddress((void**)&pm, g_om);

    convert_in1<<<B_ * (HW / 64), 256>>>(warped, ref, flows);
    prepackW<<<64, 256>>>(w1, w2, w_om);

    constexpr int ASM12 = 2 * (6 * 34 * 48) + 2 * (64 * 48);    // 25728
    constexpr int ASM3  = 2 * (4 * 34 * 48) + 2 * (224 * 48);   // 34560
    cudaFuncSetAttribute((const void*)convMMA<9, 64, 64, true, true>,
                         cudaFuncAttributeMaxDynamicSharedMemorySize, ASM12);
    cudaFuncSetAttribute((const void*)convMMA<4, 64, 64, true, true>,
                         cudaFuncAttributeMaxDynamicSharedMemorySize, ASM12);
    cudaFuncSetAttribute((const void*)convMMA<4, 216, 224, false, false>,
                         cudaFuncAttributeMaxDynamicSharedMemorySize, ASM3);

    // conv1: 144ch interleaved -> 64, lrelu, bf16 out
    convMMA<9, 64, 64, true, true><<<dim3(10 * (H / 4), B_), 256, ASM12>>>(
        in1h, in1l, wbh + W1OFF, wbl + W1OFF, b1, x2h, x2l, nullptr);
    // conv2: 64 -> 64, lrelu, bf16 out
    convMMA<4, 64, 64, true, true><<<dim3(10 * (H / 4), B_), 256, ASM12>>>(
        x2h, x2l, wbh + W2OFF, wbl + W2OFF, b2, x3h, x3l, nullptr);
    // om conv: 64 -> 216 (pad 224), fp32 NCHW out
    convMMA<4, 216, 224, false, false><<<dim3(10 * (H / 2), B_), 256, ASM3>>>(
        x3h, x3l, wbh + W3OFF, wbl + W3OFF, b_om, nullptr, nullptr, pm);

    constexpr int DCN_SMEM = (19600 + 4608) * 4;
    cudaFuncSetAttribute(dcn_kernel, cudaFuncAttributeMaxDynamicSharedMemorySize, DCN_SMEM);
    dcn_kernel<<<dim3(240, B_), 256, DCN_SMEM>>>(nbr, flows, pm, w_dcn, b_dcn, out);
}